// round 12
// baseline (speedup 1.0000x reference)
#include <cuda_runtime.h>
#include <cuda_bf16.h>
#include <cstdint>

// HyperedgeMeanAggregator: out[h,:] = mean_{e: seg_ids[e]==h} embed_table[node_idx[e],:]
// seg_ids SORTED, indices int32 (JAX x64 off).
//
// Single-kernel segment-ownership design (best structure measured: no atomics,
// no memset, no divide pass): warp w owns hyperedges [2w, 2w+2). Lanes 0/1 run
// the two range binary searches concurrently (shfl broadcast). Main loop:
// unroll-4 gather (MLP=4) with register accumulation; flush = plain STG of
// acc/cnt. Empty segments written as zeros by their owner warp.

#define FEAT   128
#define FEAT4  (FEAT / 4)     // 32 float4 per row = one warp
#define SEGW   2              // segments per warp
#define BLOCK  256            // 8 warps per block
#define WARPS  (BLOCK / 32)

__device__ __forceinline__ int lbound(const int* __restrict__ a, int n, int key) {
    int lo = 0, hi = n;
    while (lo < hi) {
        int mid = (lo + hi) >> 1;
        if (__ldg(&a[mid]) < key) lo = mid + 1; else hi = mid;
    }
    return lo;
}

__global__ __launch_bounds__(BLOCK)
void agg_kernel(const float* __restrict__ table,
                const int* __restrict__ node_idx,
                const int* __restrict__ seg_ids,
                float* __restrict__ out,
                int E, int H) {
    int gwarp = (blockIdx.x * blockDim.x + threadIdx.x) >> 5;
    int lane  = threadIdx.x & 31;

    int h_lo = gwarp * SEGW;
    if (h_lo >= H) return;
    int h_hi = h_lo + SEGW; if (h_hi > H) h_hi = H;

    // Lanes 0 and 1 search concurrently; broadcast results.
    int r = 0;
    if (lane < 2) {
        int key = (lane == 0) ? h_lo : h_hi;
        r = lbound(seg_ids, E, key);
    }
    int eb = __shfl_sync(0xffffffffu, r, 0);
    int ee = __shfl_sync(0xffffffffu, r, 1);

    const float4* t4 = reinterpret_cast<const float4*>(table);
    float4* o4 = reinterpret_cast<float4*>(out);
    const float4 zero = make_float4(0.f, 0.f, 0.f, 0.f);

    float4 acc = zero;
    float  cnt = 0.f;
    int prev = h_lo - 1;          // last h written
    int cur  = (eb < ee) ? __ldg(&seg_ids[eb]) : -1;

#define FLUSH()                                                        \
    do {                                                               \
        for (int h = prev + 1; h < cur; ++h)  /* empty segs: zeros */  \
            o4[(unsigned)h * FEAT4 + lane] = zero;                     \
        float inv = 1.0f / cnt;                                        \
        o4[(unsigned)cur * FEAT4 + lane] =                             \
            make_float4(acc.x * inv, acc.y * inv, acc.z * inv, acc.w * inv); \
        prev = cur;                                                    \
    } while (0)

#define PROC(S, V)                                                    \
    do {                                                              \
        if ((S) != cur) { FLUSH(); acc = zero; cnt = 0.f; cur = (S); }\
        acc.x += (V).x; acc.y += (V).y;                               \
        acc.z += (V).z; acc.w += (V).w;                               \
        cnt += 1.f;                                                   \
    } while (0)

    int e = eb;
    for (; e + 4 <= ee; e += 4) {
        int s0 = __ldg(&seg_ids[e + 0]), s1 = __ldg(&seg_ids[e + 1]);
        int s2 = __ldg(&seg_ids[e + 2]), s3 = __ldg(&seg_ids[e + 3]);
        unsigned n0 = (unsigned)__ldg(&node_idx[e + 0]) * FEAT4 + lane;
        unsigned n1 = (unsigned)__ldg(&node_idx[e + 1]) * FEAT4 + lane;
        unsigned n2 = (unsigned)__ldg(&node_idx[e + 2]) * FEAT4 + lane;
        unsigned n3 = (unsigned)__ldg(&node_idx[e + 3]) * FEAT4 + lane;
        // Issue all 4 row gathers before any consumption -> MLP=4.
        float4 v0 = __ldg(&t4[n0]);
        float4 v1 = __ldg(&t4[n1]);
        float4 v2 = __ldg(&t4[n2]);
        float4 v3 = __ldg(&t4[n3]);
        PROC(s0, v0); PROC(s1, v1); PROC(s2, v2); PROC(s3, v3);
    }
    for (; e < ee; ++e) {
        int s = __ldg(&seg_ids[e]);
        unsigned n = (unsigned)__ldg(&node_idx[e]) * FEAT4 + lane;
        float4 v = __ldg(&t4[n]);
        PROC(s, v);
    }

    if (cur >= 0) FLUSH();
    for (int h = prev + 1; h < h_hi; ++h)   // trailing empty segments
        o4[(unsigned)h * FEAT4 + lane] = zero;

#undef PROC
#undef FLUSH
}

extern "C" void kernel_launch(void* const* d_in, const int* in_sizes, int n_in,
                              void* d_out, int out_size) {
    const float* table    = (const float*)d_in[0];
    const int*   node_idx = (const int*)d_in[1];
    const int*   seg_ids  = (const int*)d_in[2];
    float*       out      = (float*)d_out;

    int E = in_sizes[1];
    int H = out_size / FEAT;

    int warps  = (H + SEGW - 1) / SEGW;
    int blocks = (warps + WARPS - 1) / WARPS;
    agg_kernel<<<blocks, BLOCK>>>(table, node_idx, seg_ids, out, E, H);
}

// round 13
// speedup vs baseline: 1.2413x; 1.2413x over previous
#include <cuda_runtime.h>
#include <cuda_bf16.h>
#include <cstdint>

// HyperedgeMeanAggregator: out[h,:] = mean_{e: seg_ids[e]==h} embed_table[node_idx[e],:]
// seg_ids SORTED, indices int32 (JAX x64 off).
//
// Two kernels:
//  1) seg_start[h] = lower_bound(seg_ids, h) for h in [0..H]  (50k parallel
//     binary searches, L1-hot tree) -> per-segment ranges AND counts for free.
//  2) ownership agg: warp w owns hyperedges [4w, 4w+4). Per segment: known
//     count, branch-free unroll-4 gather loop, one STG.128 flush of acc/cnt.
//     No atomics, no memset, no divide pass, no per-warp binary search.

#define FEAT   128
#define FEAT4  (FEAT / 4)     // 32 float4 per row = one warp
#define SEGW   4              // segments per warp
#define BLOCK  256            // 8 warps per block
#define WARPS  (BLOCK / 32)
#define MAX_H  65536

__device__ int g_seg_start[MAX_H + 1];

__global__ __launch_bounds__(256)
void seg_start_kernel(const int* __restrict__ seg_ids, int E, int H) {
    int h = blockIdx.x * blockDim.x + threadIdx.x;
    if (h > H) return;
    if (h == H) { g_seg_start[H] = E; return; }
    int lo = 0, hi = E;
    while (lo < hi) {
        int mid = (lo + hi) >> 1;
        if (__ldg(&seg_ids[mid]) < h) lo = mid + 1; else hi = mid;
    }
    g_seg_start[h] = lo;
}

__global__ __launch_bounds__(BLOCK)
void agg_kernel(const float* __restrict__ table,
                const int* __restrict__ node_idx,
                float* __restrict__ out,
                int H) {
    int gwarp = (blockIdx.x * blockDim.x + threadIdx.x) >> 5;
    int lane  = threadIdx.x & 31;

    int h_lo = gwarp * SEGW;
    if (h_lo >= H) return;
    int h_hi = h_lo + SEGW; if (h_hi > H) h_hi = H;

    const float4* t4 = reinterpret_cast<const float4*>(table);
    float4* o4 = reinterpret_cast<float4*>(out);

    int eb = __ldg(&g_seg_start[h_lo]);   // range start for first owned segment

    for (int h = h_lo; h < h_hi; ++h) {
        int ee = __ldg(&g_seg_start[h + 1]);
        int cnt = ee - eb;

        float4 acc = make_float4(0.f, 0.f, 0.f, 0.f);

        int e = eb;
        for (; e + 4 <= ee; e += 4) {
            unsigned n0 = (unsigned)__ldg(&node_idx[e + 0]) * FEAT4 + lane;
            unsigned n1 = (unsigned)__ldg(&node_idx[e + 1]) * FEAT4 + lane;
            unsigned n2 = (unsigned)__ldg(&node_idx[e + 2]) * FEAT4 + lane;
            unsigned n3 = (unsigned)__ldg(&node_idx[e + 3]) * FEAT4 + lane;
            // All 4 row gathers issued before consumption -> MLP=4.
            float4 v0 = __ldg(&t4[n0]);
            float4 v1 = __ldg(&t4[n1]);
            float4 v2 = __ldg(&t4[n2]);
            float4 v3 = __ldg(&t4[n3]);
            acc.x += v0.x; acc.y += v0.y; acc.z += v0.z; acc.w += v0.w;
            acc.x += v1.x; acc.y += v1.y; acc.z += v1.z; acc.w += v1.w;
            acc.x += v2.x; acc.y += v2.y; acc.z += v2.z; acc.w += v2.w;
            acc.x += v3.x; acc.y += v3.y; acc.z += v3.z; acc.w += v3.w;
        }
        for (; e < ee; ++e) {
            unsigned n = (unsigned)__ldg(&node_idx[e]) * FEAT4 + lane;
            float4 v = __ldg(&t4[n]);
            acc.x += v.x; acc.y += v.y; acc.z += v.z; acc.w += v.w;
        }

        float inv = 1.0f / (float)max(cnt, 1);     // empty segment -> zeros
        o4[(unsigned)h * FEAT4 + lane] =
            make_float4(acc.x * inv, acc.y * inv, acc.z * inv, acc.w * inv);

        eb = ee;
    }
}

extern "C" void kernel_launch(void* const* d_in, const int* in_sizes, int n_in,
                              void* d_out, int out_size) {
    const float* table    = (const float*)d_in[0];
    const int*   node_idx = (const int*)d_in[1];
    const int*   seg_ids  = (const int*)d_in[2];
    float*       out      = (float*)d_out;

    int E = in_sizes[1];
    int H = out_size / FEAT;

    // 1) per-segment start offsets (and implicit counts)
    seg_start_kernel<<<(H + 256) / 256, 256>>>(seg_ids, E, H);

    // 2) gather + per-segment mean, direct writes
    {
        int warps  = (H + SEGW - 1) / SEGW;
        int blocks = (warps + WARPS - 1) / WARPS;
        agg_kernel<<<blocks, BLOCK>>>(table, node_idx, out, H);
    }
}

// round 14
// speedup vs baseline: 1.3011x; 1.0482x over previous
#include <cuda_runtime.h>
#include <cuda_bf16.h>
#include <cstdint>

// HyperedgeMeanAggregator: out[h,:] = mean_{e: seg_ids[e]==h} embed_table[node_idx[e],:]
// seg_ids SORTED, indices int32 (JAX x64 off).
//
// Two kernels:
//  1) seg_start[h] = lower_bound(seg_ids, h)  -> ranges + counts.
//  2) ownership agg: warp w owns hyperedges [4w, 4w+4). Per segment:
//     branch-free unroll-8 gather (MLP=8), one STG.128 flush of acc/cnt.
//     No atomics, no memset, no divide pass.

#define FEAT   128
#define FEAT4  (FEAT / 4)     // 32 float4 per row = one warp
#define SEGW   4              // segments per warp
#define BLOCK  256            // 8 warps per block
#define WARPS  (BLOCK / 32)
#define MAX_H  65536

__device__ int g_seg_start[MAX_H + 1];

__global__ __launch_bounds__(256)
void seg_start_kernel(const int* __restrict__ seg_ids, int E, int H) {
    int h = blockIdx.x * blockDim.x + threadIdx.x;
    if (h > H) return;
    if (h == H) { g_seg_start[H] = E; return; }
    int lo = 0, hi = E;
    while (lo < hi) {
        int mid = (lo + hi) >> 1;
        if (__ldg(&seg_ids[mid]) < h) lo = mid + 1; else hi = mid;
    }
    g_seg_start[h] = lo;
}

__global__ __launch_bounds__(BLOCK)
void agg_kernel(const float* __restrict__ table,
                const int* __restrict__ node_idx,
                float* __restrict__ out,
                int H) {
    int gwarp = (blockIdx.x * blockDim.x + threadIdx.x) >> 5;
    int lane  = threadIdx.x & 31;

    int h_lo = gwarp * SEGW;
    if (h_lo >= H) return;
    int h_hi = h_lo + SEGW; if (h_hi > H) h_hi = H;

    const float4* t4 = reinterpret_cast<const float4*>(table);
    float4* o4 = reinterpret_cast<float4*>(out);

    int eb = __ldg(&g_seg_start[h_lo]);

    for (int h = h_lo; h < h_hi; ++h) {
        int ee = __ldg(&g_seg_start[h + 1]);
        int cnt = ee - eb;

        float4 acc = make_float4(0.f, 0.f, 0.f, 0.f);

        int e = eb;
        for (; e + 8 <= ee; e += 8) {
            unsigned n0 = (unsigned)__ldg(&node_idx[e + 0]) * FEAT4 + lane;
            unsigned n1 = (unsigned)__ldg(&node_idx[e + 1]) * FEAT4 + lane;
            unsigned n2 = (unsigned)__ldg(&node_idx[e + 2]) * FEAT4 + lane;
            unsigned n3 = (unsigned)__ldg(&node_idx[e + 3]) * FEAT4 + lane;
            unsigned n4 = (unsigned)__ldg(&node_idx[e + 4]) * FEAT4 + lane;
            unsigned n5 = (unsigned)__ldg(&node_idx[e + 5]) * FEAT4 + lane;
            unsigned n6 = (unsigned)__ldg(&node_idx[e + 6]) * FEAT4 + lane;
            unsigned n7 = (unsigned)__ldg(&node_idx[e + 7]) * FEAT4 + lane;
            // All 8 row gathers issued before any consumption -> MLP=8.
            float4 v0 = __ldg(&t4[n0]);
            float4 v1 = __ldg(&t4[n1]);
            float4 v2 = __ldg(&t4[n2]);
            float4 v3 = __ldg(&t4[n3]);
            float4 v4 = __ldg(&t4[n4]);
            float4 v5 = __ldg(&t4[n5]);
            float4 v6 = __ldg(&t4[n6]);
            float4 v7 = __ldg(&t4[n7]);
            acc.x += v0.x; acc.y += v0.y; acc.z += v0.z; acc.w += v0.w;
            acc.x += v1.x; acc.y += v1.y; acc.z += v1.z; acc.w += v1.w;
            acc.x += v2.x; acc.y += v2.y; acc.z += v2.z; acc.w += v2.w;
            acc.x += v3.x; acc.y += v3.y; acc.z += v3.z; acc.w += v3.w;
            acc.x += v4.x; acc.y += v4.y; acc.z += v4.z; acc.w += v4.w;
            acc.x += v5.x; acc.y += v5.y; acc.z += v5.z; acc.w += v5.w;
            acc.x += v6.x; acc.y += v6.y; acc.z += v6.z; acc.w += v6.w;
            acc.x += v7.x; acc.y += v7.y; acc.z += v7.z; acc.w += v7.w;
        }
        if (e + 4 <= ee) {
            unsigned n0 = (unsigned)__ldg(&node_idx[e + 0]) * FEAT4 + lane;
            unsigned n1 = (unsigned)__ldg(&node_idx[e + 1]) * FEAT4 + lane;
            unsigned n2 = (unsigned)__ldg(&node_idx[e + 2]) * FEAT4 + lane;
            unsigned n3 = (unsigned)__ldg(&node_idx[e + 3]) * FEAT4 + lane;
            float4 v0 = __ldg(&t4[n0]);
            float4 v1 = __ldg(&t4[n1]);
            float4 v2 = __ldg(&t4[n2]);
            float4 v3 = __ldg(&t4[n3]);
            acc.x += v0.x; acc.y += v0.y; acc.z += v0.z; acc.w += v0.w;
            acc.x += v1.x; acc.y += v1.y; acc.z += v1.z; acc.w += v1.w;
            acc.x += v2.x; acc.y += v2.y; acc.z += v2.z; acc.w += v2.w;
            acc.x += v3.x; acc.y += v3.y; acc.z += v3.z; acc.w += v3.w;
            e += 4;
        }
        for (; e < ee; ++e) {
            unsigned n = (unsigned)__ldg(&node_idx[e]) * FEAT4 + lane;
            float4 v = __ldg(&t4[n]);
            acc.x += v.x; acc.y += v.y; acc.z += v.z; acc.w += v.w;
        }

        float inv = 1.0f / (float)max(cnt, 1);     // empty segment -> zeros
        o4[(unsigned)h * FEAT4 + lane] =
            make_float4(acc.x * inv, acc.y * inv, acc.z * inv, acc.w * inv);

        eb = ee;
    }
}

extern "C" void kernel_launch(void* const* d_in, const int* in_sizes, int n_in,
                              void* d_out, int out_size) {
    const float* table    = (const float*)d_in[0];
    const int*   node_idx = (const int*)d_in[1];
    const int*   seg_ids  = (const int*)d_in[2];
    float*       out      = (float*)d_out;

    int E = in_sizes[1];
    int H = out_size / FEAT;

    // 1) per-segment start offsets (and implicit counts)
    seg_start_kernel<<<(H + 256) / 256, 256>>>(seg_ids, E, H);

    // 2) gather + per-segment mean, direct writes
    {
        int warps  = (H + SEGW - 1) / SEGW;
        int blocks = (warps + WARPS - 1) / WARPS;
        agg_kernel<<<blocks, BLOCK>>>(table, node_idx, out, H);
    }
}